// round 12
// baseline (speedup 1.0000x reference)
#include <cuda_runtime.h>
#include <cuda_bf16.h>
#include <math.h>

#define MAX_E 640000
#define MAX_N 50000
#define VDIM  128
#define CAP   128   // per-segment capacity (deg ~ Poisson(12.8), max ~45)

// -------- scratch (device globals: allocations forbidden) --------
__device__ float g_keys_proj[MAX_N * VDIM];
__device__ float g_probs[MAX_E];
__device__ float g_d[MAX_N];
__device__ int   g_cursor[MAX_N];
__device__ int   g_edge_slots[MAX_N * CAP];
__device__ uint4 g_Wfrag[8 * 16 * 32];   // fragment-major split W: 64 KB

// -------- kernel 0: zero cursors --------
__global__ void zero_cursor_kernel(int n) {
    int i = blockIdx.x * blockDim.x + threadIdx.x;
    if (i < n) g_cursor[i] = 0;
}

// -------- kernel 1: bucket edges by segment --------
__global__ __launch_bounds__(256)
void fill_kernel(const int* __restrict__ indices, int E) {
    int e = blockIdx.x * blockDim.x + threadIdx.x;
    if (e >= E) return;
    int n = indices[e];
    int slot = atomicAdd(&g_cursor[n], 1);
    if (slot < CAP) g_edge_slots[n * CAP + slot] = e;
}

// -------- kernel 1b: split W into bf16 hi/lo, FRAGMENT-MAJOR layout --------
// Fragment (kk, j, lane): lane = 4g + q reads, for v = j*8+g, k0 = kk*16:
//   bh0 = Whi[v][k0+2q..+1]  bh1 = Whi[v][k0+8+2q..+1]
//   bl0 = Wlo[v][k0+2q..+1]  bl1 = Wlo[v][k0+8+2q..+1]
// packed as uint4 {bh0, bh1, bl0, bl1} at index ((kk*16+j)*32 + lane).
__device__ __forceinline__ unsigned pack2_hi(float x, float y) {
    __nv_bfloat162 h = __floats2bfloat162_rn(x, y);
    return *(unsigned*)&h;
}
__device__ __forceinline__ unsigned pack2_lo(float x, float y) {
    float lx = x - __bfloat162float(__float2bfloat16(x));
    float ly = y - __bfloat162float(__float2bfloat16(y));
    __nv_bfloat162 l = __floats2bfloat162_rn(lx, ly);
    return *(unsigned*)&l;
}
__global__ __launch_bounds__(256)
void splitW_kernel(const float* __restrict__ W) {
    int idx = blockIdx.x * blockDim.x + threadIdx.x;
    if (idx >= 8 * 16 * 32) return;
    int lane = idx & 31;
    int j    = (idx >> 5) & 15;
    int kk   = idx >> 9;
    int g = lane >> 2, q = lane & 3;
    int v = j * 8 + g, k0 = kk * 16;
    const float* src = W + v * VDIM + k0 + 2 * q;
    float x0 = src[0], x1 = src[1], x2 = src[8], x3 = src[9];
    uint4 f;
    f.x = pack2_hi(x0, x1);
    f.y = pack2_hi(x2, x3);
    f.z = pack2_lo(x0, x1);
    f.w = pack2_lo(x2, x3);
    g_Wfrag[idx] = f;
}

// -------- kernel 2: tensor-core split-bf16 GEMM --------
// keys_proj[n][v] = sum_k A[n][k]*W[v][k] + b[v];  D = Ah*Wh + Ah*Wl + Al*Wh
#define GEMM_ROWS 128
#define GEMM_SMEM (4096 * 16 + 128 * 4)

__device__ __forceinline__ void mma_bf16(float* c, const unsigned* a,
                                         unsigned b0, unsigned b1) {
    asm volatile(
        "mma.sync.aligned.m16n8k16.row.col.f32.bf16.bf16.f32 "
        "{%0,%1,%2,%3}, {%4,%5,%6,%7}, {%8,%9}, {%0,%1,%2,%3};"
        : "+f"(c[0]), "+f"(c[1]), "+f"(c[2]), "+f"(c[3])
        : "r"(a[0]), "r"(a[1]), "r"(a[2]), "r"(a[3]), "r"(b0), "r"(b1));
}

__global__ __launch_bounds__(256)
void gemm_tc_kernel(const float* __restrict__ A,    // [N,128] attn_keys
                    const float* __restrict__ bias,
                    int N) {
    extern __shared__ __align__(16) char smem_raw[];
    uint4* sWf  = (uint4*)smem_raw;                  // [4096] fragment-major W
    float* sbias = (float*)(sWf + 4096);

    const int t = threadIdx.x;
    const int block_row = blockIdx.x * GEMM_ROWS;

    // coalesced copy of pre-split fragment-major W (64 KB)
    for (int i = t; i < 4096; i += 256) sWf[i] = g_Wfrag[i];
    if (t < 128) sbias[t] = bias[t];
    __syncthreads();

    const int warp = t >> 5;
    const int lane = t & 31;
    const int g = lane >> 2;
    const int q = lane & 3;

    const int r0 = block_row + warp * 16 + g;
    const int r1 = r0 + 8;
    const bool v0 = (r0 < N), v1 = (r1 < N);
    const float* A0 = A + (size_t)r0 * VDIM + 2 * q;
    const float* A1 = A + (size_t)r1 * VDIM + 2 * q;

    float acc[16][4];
    #pragma unroll
    for (int j = 0; j < 16; j++)
        #pragma unroll
        for (int i = 0; i < 4; i++) acc[j][i] = 0.f;

    const float2 Z = make_float2(0.f, 0.f);
    float2 c00 = v0 ? *(const float2*)(A0)     : Z;
    float2 c10 = v1 ? *(const float2*)(A1)     : Z;
    float2 c01 = v0 ? *(const float2*)(A0 + 8) : Z;
    float2 c11 = v1 ? *(const float2*)(A1 + 8) : Z;

    #pragma unroll
    for (int kk = 0; kk < 8; kk++) {
        unsigned ah[4], al[4];
        ah[0] = pack2_hi(c00.x, c00.y); al[0] = pack2_lo(c00.x, c00.y);
        ah[1] = pack2_hi(c10.x, c10.y); al[1] = pack2_lo(c10.x, c10.y);
        ah[2] = pack2_hi(c01.x, c01.y); al[2] = pack2_lo(c01.x, c01.y);
        ah[3] = pack2_hi(c11.x, c11.y); al[3] = pack2_lo(c11.x, c11.y);

        if (kk < 7) {   // prefetch next A k-slab; overlaps MMA loop
            int k0 = (kk + 1) * 16;
            c00 = v0 ? *(const float2*)(A0 + k0)     : Z;
            c10 = v1 ? *(const float2*)(A1 + k0)     : Z;
            c01 = v0 ? *(const float2*)(A0 + k0 + 8) : Z;
            c11 = v1 ? *(const float2*)(A1 + k0 + 8) : Z;
        }

        const uint4* wf = sWf + kk * 512 + lane;
        #pragma unroll
        for (int j = 0; j < 16; j++) {
            uint4 f = wf[j * 32];     // one LDS.128, conflict-free
            mma_bf16(acc[j], ah, f.x, f.y);
            mma_bf16(acc[j], ah, f.z, f.w);
            mma_bf16(acc[j], al, f.x, f.y);
        }
    }

    #pragma unroll
    for (int j = 0; j < 16; j++) {
        int col = j * 8 + q * 2;
        float b0 = sbias[col], b1 = sbias[col + 1];
        if (v0)
            *(float2*)&g_keys_proj[(size_t)r0 * VDIM + col] =
                make_float2(acc[j][0] + b0, acc[j][1] + b1);
        if (v1)
            *(float2*)&g_keys_proj[(size_t)r1 * VDIM + col] =
                make_float2(acc[j][2] + b0, acc[j][3] + b1);
    }
}

// -------- kernel 3: warp-per-segment, simple loop, depth-2 prefetch --------
__global__ __launch_bounds__(256)
void segment_kernel(const float4* __restrict__ sv,
                    float* __restrict__ attn_out,
                    int N) {
    const unsigned FULL = 0xffffffffu;
    int n = (blockIdx.x * blockDim.x + threadIdx.x) >> 5;
    int lane = threadIdx.x & 31;
    if (n >= N) return;

    int deg = g_cursor[n];
    if (deg > CAP) deg = CAP;

    const float4* kp = (const float4*)g_keys_proj;
    float4 b = kp[(size_t)n * 32 + lane];

    int eids[4];
    #pragma unroll
    for (int t = 0; t < 4; t++) {
        int j = t * 32 + lane;
        eids[t] = (j < deg) ? g_edge_slots[n * CAP + j] : 0;
    }

    float d = 0.f;
    float4 acc = make_float4(0.f, 0.f, 0.f, 0.f);

    // depth-2 prefetch ring: two sv rows in flight
    int eA = 0, eB = 0;
    float4 aA = make_float4(0.f, 0.f, 0.f, 0.f);
    float4 aB = aA;
    if (deg > 0) {
        eA = __shfl_sync(FULL, eids[0], 0);
        aA = sv[(size_t)eA * 32 + lane];
    }
    if (deg > 1) {
        eB = __shfl_sync(FULL, eids[0], 1);
        aB = sv[(size_t)eB * 32 + lane];
    }

    for (int j = 0; j < deg; j++) {
        float4 a = aA;
        int e = eA;
        eA = eB; aA = aB;
        int jj = j + 2;
        if (jj < deg) {
            eB = __shfl_sync(FULL, eids[jj >> 5], jj & 31);
            aB = sv[(size_t)eB * 32 + lane];
        }

        float p = fmaf(a.x, b.x, fmaf(a.y, b.y, fmaf(a.z, b.z, a.w * b.w)));
        #pragma unroll
        for (int o = 16; o > 0; o >>= 1) p += __shfl_xor_sync(FULL, p, o);

        if (lane == 0) g_probs[e] = p;

        float w = __expf(p);
        d += w;
        acc.x = fmaf(a.x, w, acc.x);
        acc.y = fmaf(a.y, w, acc.y);
        acc.z = fmaf(a.z, w, acc.z);
        acc.w = fmaf(a.w, w, acc.w);
    }

    float inv = (deg > 0) ? __fdividef(1.0f, d) : 0.0f;
    ((float4*)attn_out)[(size_t)n * 32 + lane] =
        make_float4(acc.x * inv, acc.y * inv, acc.z * inv, acc.w * inv);
    if (lane == 0) g_d[n] = d;
}

// -------- kernel 4: scores[e] = exp(p[e]) / d[n] --------
__global__ __launch_bounds__(256)
void scores_kernel(const int* __restrict__ indices,
                   float* __restrict__ scores_out,
                   int E) {
    int e = blockIdx.x * blockDim.x + threadIdx.x;
    if (e >= E) return;
    int n = __ldg(&indices[e]);
    scores_out[e] = __fdividef(__expf(g_probs[e]), g_d[n]);
}

extern "C" void kernel_launch(void* const* d_in, const int* in_sizes, int n_in,
                              void* d_out, int out_size) {
    const float* sv      = (const float*)d_in[0];
    const int*   indices = (const int*)d_in[1];
    const float* akeys   = (const float*)d_in[2];
    const float* W       = (const float*)d_in[3];
    const float* bias    = (const float*)d_in[4];

    int E = in_sizes[1];
    int N = in_sizes[2] / VDIM;

    float* scores_out = (float*)d_out;
    float* attn_out   = (float*)d_out + E;

    zero_cursor_kernel<<<(N + 255) / 256, 256>>>(N);
    splitW_kernel<<<(8 * 16 * 32 + 255) / 256, 256>>>(W);
    fill_kernel<<<(E + 255) / 256, 256>>>(indices, E);

    cudaFuncSetAttribute(gemm_tc_kernel,
                         cudaFuncAttributeMaxDynamicSharedMemorySize, GEMM_SMEM);
    gemm_tc_kernel<<<(N + GEMM_ROWS - 1) / GEMM_ROWS, 256, GEMM_SMEM>>>(
        akeys, bias, N);

    segment_kernel<<<(N * 32 + 255) / 256, 256>>>((const float4*)sv, attn_out, N);

    scores_kernel<<<(E + 255) / 256, 256>>>(indices, scores_out, E);
}

// round 15
// speedup vs baseline: 1.0705x; 1.0705x over previous
#include <cuda_runtime.h>
#include <cuda_bf16.h>
#include <math.h>

#define MAX_E 640000
#define MAX_N 50000
#define VDIM  128
#define CAP   128   // per-segment capacity (deg ~ Poisson(12.8), max ~45)

// -------- scratch (device globals: allocations forbidden) --------
__device__ float         g_keys_proj[MAX_N * VDIM];
__device__ float         g_probs[MAX_E];
__device__ float         g_d[MAX_N];
__device__ int           g_cursor[MAX_N];
__device__ int           g_edge_slots[MAX_N * CAP];
__device__ __nv_bfloat16 g_Whi[VDIM * VDIM];   // pre-split W (hi)
__device__ __nv_bfloat16 g_Wlo[VDIM * VDIM];   // pre-split W (lo residual)

// -------- kernel 0: zero cursors --------
__global__ void zero_cursor_kernel(int n) {
    int i = blockIdx.x * blockDim.x + threadIdx.x;
    if (i < n) g_cursor[i] = 0;
}

// -------- kernel 1: bucket edges by segment --------
__global__ __launch_bounds__(256)
void fill_kernel(const int* __restrict__ indices, int E) {
    int e = blockIdx.x * blockDim.x + threadIdx.x;
    if (e >= E) return;
    int n = indices[e];
    int slot = atomicAdd(&g_cursor[n], 1);
    if (slot < CAP) g_edge_slots[n * CAP + slot] = e;
}

// -------- kernel 1b: split W into bf16 hi/lo (once) --------
__global__ __launch_bounds__(256)
void splitW_kernel(const float* __restrict__ W) {
    int i = blockIdx.x * blockDim.x + threadIdx.x;
    if (i >= VDIM * VDIM) return;
    float w = W[i];
    __nv_bfloat16 h = __float2bfloat16(w);
    g_Whi[i] = h;
    g_Wlo[i] = __float2bfloat16(w - __bfloat162float(h));
}

// -------- kernel 2: tensor-core split-bf16 GEMM --------
// keys_proj[n][v] = sum_k A[n][k]*W[v][k] + b[v];  D = Ah*Wh + Ah*Wl + Al*Wh
// 64 rows/block, 8 warps = 4 row-groups x 2 col-halves -> ~72 regs, 3 blocks/SM.
#define GEMM_ROWS 64
#define WPAD      136   // bf16 row stride -> bank 4g+q, conflict-free
#define GEMM_SMEM (2 * 128 * WPAD * 2 + 128 * 4)

__device__ __forceinline__ void mma_bf16(float* c, const unsigned* a,
                                         unsigned b0, unsigned b1) {
    asm volatile(
        "mma.sync.aligned.m16n8k16.row.col.f32.bf16.bf16.f32 "
        "{%0,%1,%2,%3}, {%4,%5,%6,%7}, {%8,%9}, {%0,%1,%2,%3};"
        : "+f"(c[0]), "+f"(c[1]), "+f"(c[2]), "+f"(c[3])
        : "r"(a[0]), "r"(a[1]), "r"(a[2]), "r"(a[3]), "r"(b0), "r"(b1));
}

__device__ __forceinline__ unsigned pack2_hi(float x, float y) {
    __nv_bfloat162 h = __floats2bfloat162_rn(x, y);
    return *(unsigned*)&h;
}
__device__ __forceinline__ unsigned pack2_lo(float x, float y) {
    float lx = x - __bfloat162float(__float2bfloat16(x));
    float ly = y - __bfloat162float(__float2bfloat16(y));
    __nv_bfloat162 l = __floats2bfloat162_rn(lx, ly);
    return *(unsigned*)&l;
}

__global__ __launch_bounds__(256)
void gemm_tc_kernel(const float* __restrict__ A,    // [N,128] attn_keys
                    const float* __restrict__ bias,
                    int N) {
    extern __shared__ __align__(16) char smem_raw[];
    __nv_bfloat16* W_hi = (__nv_bfloat16*)smem_raw;          // [128][WPAD]
    __nv_bfloat16* W_lo = W_hi + 128 * WPAD;
    float* sbias = (float*)(W_lo + 128 * WPAD);

    const int t = threadIdx.x;
    const int block_row = blockIdx.x * GEMM_ROWS;

    // Copy pre-split W into padded smem (uint4 = 8 bf16)
    for (int i = t; i < 128 * 16; i += 256) {
        int row = i >> 4, c = i & 15;
        ((uint4*)(W_hi + row * WPAD))[c] = ((const uint4*)(g_Whi + row * VDIM))[c];
        ((uint4*)(W_lo + row * WPAD))[c] = ((const uint4*)(g_Wlo + row * VDIM))[c];
    }
    if (t < 128) sbias[t] = bias[t];
    __syncthreads();

    const int warp = t >> 5;
    const int lane = t & 31;
    const int g = lane >> 2;
    const int q = lane & 3;
    const int rg = warp & 3;        // row-group 0..3
    const int jh = warp >> 2;       // col-half 0..1 (j in [jh*8, jh*8+8))

    const int r0 = block_row + rg * 16 + g;
    const int r1 = r0 + 8;
    const bool v0 = (r0 < N), v1 = (r1 < N);
    const float* A0 = A + (size_t)r0 * VDIM + 2 * q;
    const float* A1 = A + (size_t)r1 * VDIM + 2 * q;

    float acc[8][4];
    #pragma unroll
    for (int j = 0; j < 8; j++)
        #pragma unroll
        for (int i = 0; i < 4; i++) acc[j][i] = 0.f;

    const float2 Z = make_float2(0.f, 0.f);
    float2 c00 = v0 ? *(const float2*)(A0)     : Z;
    float2 c10 = v1 ? *(const float2*)(A1)     : Z;
    float2 c01 = v0 ? *(const float2*)(A0 + 8) : Z;
    float2 c11 = v1 ? *(const float2*)(A1 + 8) : Z;

    #pragma unroll
    for (int kk = 0; kk < 8; kk++) {
        unsigned ah[4], al[4];
        ah[0] = pack2_hi(c00.x, c00.y); al[0] = pack2_lo(c00.x, c00.y);
        ah[1] = pack2_hi(c10.x, c10.y); al[1] = pack2_lo(c10.x, c10.y);
        ah[2] = pack2_hi(c01.x, c01.y); al[2] = pack2_lo(c01.x, c01.y);
        ah[3] = pack2_hi(c11.x, c11.y); al[3] = pack2_lo(c11.x, c11.y);

        if (kk < 7) {   // prefetch next A k-slab; overlaps MMA loop
            int k0 = (kk + 1) * 16;
            c00 = v0 ? *(const float2*)(A0 + k0)     : Z;
            c10 = v1 ? *(const float2*)(A1 + k0)     : Z;
            c01 = v0 ? *(const float2*)(A0 + k0 + 8) : Z;
            c11 = v1 ? *(const float2*)(A1 + k0 + 8) : Z;
        }

        int kb = kk * 16 + q * 2;
        #pragma unroll
        for (int j = 0; j < 8; j++) {
            int v = (jh * 8 + j) * 8 + g;
            unsigned bh0 = *(const unsigned*)&W_hi[v * WPAD + kb];
            unsigned bh1 = *(const unsigned*)&W_hi[v * WPAD + kb + 8];
            unsigned bl0 = *(const unsigned*)&W_lo[v * WPAD + kb];
            unsigned bl1 = *(const unsigned*)&W_lo[v * WPAD + kb + 8];
            mma_bf16(acc[j], ah, bh0, bh1);
            mma_bf16(acc[j], ah, bl0, bl1);
            mma_bf16(acc[j], al, bh0, bh1);
        }
    }

    #pragma unroll
    for (int j = 0; j < 8; j++) {
        int col = (jh * 8 + j) * 8 + q * 2;
        float b0 = sbias[col], b1 = sbias[col + 1];
        if (v0)
            *(float2*)&g_keys_proj[(size_t)r0 * VDIM + col] =
                make_float2(acc[j][0] + b0, acc[j][1] + b1);
        if (v1)
            *(float2*)&g_keys_proj[(size_t)r1 * VDIM + col] =
                make_float2(acc[j][2] + b0, acc[j][3] + b1);
    }
}

// -------- kernel 3: warp-per-segment, simple loop + depth-1 prefetch (R10 best) --------
__global__ __launch_bounds__(256)
void segment_kernel(const float4* __restrict__ sv,
                    float* __restrict__ attn_out,
                    int N) {
    const unsigned FULL = 0xffffffffu;
    int n = (blockIdx.x * blockDim.x + threadIdx.x) >> 5;
    int lane = threadIdx.x & 31;
    if (n >= N) return;

    int deg = g_cursor[n];
    if (deg > CAP) deg = CAP;

    const float4* kp = (const float4*)g_keys_proj;
    float4 b = kp[(size_t)n * 32 + lane];

    int eids[4];
    #pragma unroll
    for (int t = 0; t < 4; t++) {
        int j = t * 32 + lane;
        eids[t] = (j < deg) ? g_edge_slots[n * CAP + j] : 0;
    }

    float d = 0.f;
    float4 acc = make_float4(0.f, 0.f, 0.f, 0.f);

    int e_next = __shfl_sync(FULL, eids[0], 0);
    float4 a_next = make_float4(0.f, 0.f, 0.f, 0.f);
    if (deg > 0) a_next = sv[(size_t)e_next * 32 + lane];

    for (int j = 0; j < deg; j++) {
        float4 a = a_next;
        int e = e_next;
        int jj = j + 1;
        if (jj < deg) {
            e_next = __shfl_sync(FULL, eids[jj >> 5], jj & 31);
            a_next = sv[(size_t)e_next * 32 + lane];
        }

        float p = fmaf(a.x, b.x, fmaf(a.y, b.y, fmaf(a.z, b.z, a.w * b.w)));
        #pragma unroll
        for (int o = 16; o > 0; o >>= 1) p += __shfl_xor_sync(FULL, p, o);

        if (lane == 0) g_probs[e] = p;

        float w = __expf(p);
        d += w;
        acc.x = fmaf(a.x, w, acc.x);
        acc.y = fmaf(a.y, w, acc.y);
        acc.z = fmaf(a.z, w, acc.z);
        acc.w = fmaf(a.w, w, acc.w);
    }

    float inv = (deg > 0) ? __fdividef(1.0f, d) : 0.0f;
    ((float4*)attn_out)[(size_t)n * 32 + lane] =
        make_float4(acc.x * inv, acc.y * inv, acc.z * inv, acc.w * inv);
    if (lane == 0) g_d[n] = d;
}

// -------- kernel 4: scores[e] = exp(p[e]) / d[n] --------
__global__ __launch_bounds__(256)
void scores_kernel(const int* __restrict__ indices,
                   float* __restrict__ scores_out,
                   int E) {
    int e = blockIdx.x * blockDim.x + threadIdx.x;
    if (e >= E) return;
    int n = __ldg(&indices[e]);
    scores_out[e] = __fdividef(__expf(g_probs[e]), g_d[n]);
}

extern "C" void kernel_launch(void* const* d_in, const int* in_sizes, int n_in,
                              void* d_out, int out_size) {
    const float* sv      = (const float*)d_in[0];
    const int*   indices = (const int*)d_in[1];
    const float* akeys   = (const float*)d_in[2];
    const float* W       = (const float*)d_in[3];
    const float* bias    = (const float*)d_in[4];

    int E = in_sizes[1];
    int N = in_sizes[2] / VDIM;

    float* scores_out = (float*)d_out;
    float* attn_out   = (float*)d_out + E;

    zero_cursor_kernel<<<(N + 255) / 256, 256>>>(N);
    splitW_kernel<<<(VDIM * VDIM + 255) / 256, 256>>>(W);
    fill_kernel<<<(E + 255) / 256, 256>>>(indices, E);

    cudaFuncSetAttribute(gemm_tc_kernel,
                         cudaFuncAttributeMaxDynamicSharedMemorySize, GEMM_SMEM);
    gemm_tc_kernel<<<(N + GEMM_ROWS - 1) / GEMM_ROWS, 256, GEMM_SMEM>>>(
        akeys, bias, N);

    segment_kernel<<<(N * 32 + 255) / 256, 256>>>((const float4*)sv, attn_out, N);

    scores_kernel<<<(E + 255) / 256, 256>>>(indices, scores_out, E);
}